// round 6
// baseline (speedup 1.0000x reference)
#include <cuda_runtime.h>
#include <math.h>

#define NT 64      // targets
#define NA 3       // anchors per level
#define NCLS 80
#define NB 8       // batch

#define H0 76
#define H1 38
#define H2 19
#define HW0 (H0*H0)
#define HW1 (H1*H1)
#define HW2 (H2*H2)
#define NC0 (NB*NA*HW0)   // 138624
#define NC1 (NB*NA*HW1)   // 34656
#define NC2 (NB*NA*HW2)   // 8664
#define NCALL (NC0+NC1+NC2) // 181944

#define NBLK 148
#define TPB  512
#define NWARP (TPB/32)      // 16
#define NGATHER (3*NT*NA)   // 576 warp tasks -> blocks 0..35

#define IOU_T 0.213f
#define IGN_T 0.7f
#define COORD_SCALE 0.07f
#define FOUR_OVER_PI2 0.4052847345693511f

__constant__ float c_anch[3][3][2] = {
    {{1.5f, 2.0f}, {2.375f, 4.5f}, {5.0f, 3.5f}},
    {{2.25f, 4.6875f}, {4.75f, 3.4375f}, {4.5f, 9.125f}},
    {{4.4375f, 3.4375f}, {6.0f, 7.59375f}, {14.34375f, 12.53125f}}
};
__constant__ float c_invred[3] = {0.125f, 0.0625f, 0.03125f};
__constant__ float c_xysc[3]   = {1.2f, 1.1f, 1.05f};

// cross-block accumulators + ticket (zero at load; reset by last block each run)
__device__ float g_acc[3];
__device__ int   g_ticket;

__device__ __forceinline__ float softplusf(float x) {
    return fmaxf(x, 0.0f) + __logf(1.0f + __expf(-fabsf(x)));
}

// ---------------------------------------------------------------------------
// Cell: returns softplus(obj) if this cell is a negative, else 0.
// Level-local cell id. Templated => constant div/mod and strides.
// ---------------------------------------------------------------------------
template<int LVL>
__device__ __forceinline__ float cell_obj(const float* __restrict__ pred, int cell,
    const float4* __restrict__ s_box, const float2* __restrict__ s_meta,
    const int* __restrict__ s_start)
{
    constexpr int   Hd  = (LVL==0) ? H0 : (LVL==1) ? H1 : H2;
    constexpr int   HWc = Hd * Hd;
    constexpr float xys = (LVL==0) ? 1.2f : (LVL==1) ? 1.1f : 1.05f;
    constexpr float off = 0.5f * (xys - 1.0f);

    int x = cell % Hd;
    int r = cell / Hd;
    int y = r % Hd;  r /= Hd;
    int a = r % NA;
    int b = r / NA;

    const float* pb = pred + ((b*NA + a)*85)*HWc + y*Hd + x;
    float px = pb[0], py = pb[HWc], pw = pb[2*HWc], ph = pb[3*HWc], po = pb[4*HWc];

    float bx = __fdividef(xys, 1.0f + __expf(-px)) - off + (float)x;
    float by = __fdividef(xys, 1.0f + __expf(-py)) - off + (float)y;
    float bw = __expf(pw) * c_anch[LVL][a][0];
    float bh = __expf(ph) * c_anch[LVL][a][1];
    float bx1 = bx - bw*0.5f, bx2 = bx + bw*0.5f;
    float by1 = by - bh*0.5f, by2 = by + bh*0.5f;
    float rhs_c = IGN_T * (bw*bh + 1e-16f);

    int key = x | (y << 8);
    bool dead = false;
    int lo = s_start[b], hi = s_start[b+1];    // warp-uniform in interior
    for (int t = lo; t < hi; t++) {
        float4 tb = s_box[t];                  // corners x1,y1,x2,y2
        float2 tm = s_meta[t];                 // (area, packed meta)
        float ix = fminf(bx2, tb.z) - fmaxf(bx1, tb.x);
        float iy = fminf(by2, tb.w) - fmaxf(by1, tb.y);
        float inter = fmaxf(ix, 0.0f) * fmaxf(iy, 0.0f);
        // iou > IG  <=>  inter*(1+IG) > IG*(barea + tarea + eps)
        bool c1 = inter * (1.0f + IGN_T) > fmaf(IGN_T, tm.x, rhs_c);
        int mm = __float_as_int(tm.y);         // ti | tj<<8 | match<<16
        bool c2 = ((mm & 0xffff) == key) && (((mm >> (16 + a)) & 1) != 0);
        dead = dead | c1 | c2;
    }
    return dead ? 0.0f : softplusf(po);
}

// ---------------------------------------------------------------------------
// Persistent single-wave kernel: 148 blocks x 512 threads.
// Prelude (all 3 levels) once per block; then grid-stride over all cells.
// First 576 warps (blocks 0..35) also each run one gather task.
// ---------------------------------------------------------------------------
__global__ void __launch_bounds__(TPB)
yolo_kernel(const float* __restrict__ p0, const float* __restrict__ p1,
            const float* __restrict__ p2, const float* __restrict__ targets,
            const int* __restrict__ cats, float* __restrict__ out)
{
    __shared__ float  s_raw[NT*5];
    __shared__ float4 s_box[3][NT];    // sorted corners per level
    __shared__ float2 s_meta[3][NT];   // sorted (area, meta) per level
    __shared__ float4 s_gbox[3][NT];   // unsorted cx,cy,w,h per level (gather)
    __shared__ int    s_gm[3][NT];     // unsorted packed meta per level (gather)
    __shared__ int    s_start[3][NB+1];
    __shared__ int    s_off[3][NB];
    __shared__ float  s_warp[NWARP];
    __shared__ float  s_acc[3];
    __shared__ bool   s_last;

    int tid = threadIdx.x;
    int blk = blockIdx.x;
    int warp = tid >> 5, lane = tid & 31;

    // ---- stage + zero ----
    for (int i = tid; i < NT*5; i += TPB) s_raw[i] = targets[i];
    if (tid < 3*(NB+1)) ((int*)s_start)[tid] = 0;
    if (tid < 3)        s_acc[tid] = 0.0f;
    __syncthreads();

    // ---- per-(level,target) preprocessing: threads 0..191 ----
    float cx = 0.f, cy = 0.f, w = 0.f, h = 0.f;
    int bid = 0, ti = 0, tj = 0, match = 0, lv = 0, tt = 0;
    if (tid < 3*NT) {
        lv = tid / NT;  tt = tid % NT;
        float ir = c_invred[lv];
        float x1 = s_raw[tt*5+0]*ir, y1 = s_raw[tt*5+1]*ir;
        float x2 = s_raw[tt*5+2]*ir, y2 = s_raw[tt*5+3]*ir;
        bid = (int)s_raw[tt*5+4];
        w = x2 - x1;  h = y2 - y1;
        cx = (x1 + x2)*0.5f;  cy = (y1 + y2)*0.5f;
        ti = (int)cx;  tj = (int)cy;
        float ta = w*h;
        float ious[NA]; float best = -1.0f; int bi = 0;
        #pragma unroll
        for (int a = 0; a < NA; a++) {
            float aw = c_anch[lv][a][0], ah = c_anch[lv][a][1];
            float inter = fminf(aw, w) * fminf(ah, h);
            float iou = inter / (aw*ah + ta - inter);
            ious[a] = iou;
            if (iou > best) { best = iou; bi = a; }   // first-max == argmax
        }
        #pragma unroll
        for (int a = 0; a < NA; a++)
            if (ious[a] > IOU_T || a == bi) match |= 1 << a;

        s_gbox[lv][tt] = make_float4(cx, cy, w, h);
        s_gm[lv][tt]   = ti | (tj << 8) | (match << 16) | (bid << 19);
        atomicAdd(&s_start[lv][bid+1], 1);
    }
    __syncthreads();
    if (tid < 3) {
        #pragma unroll
        for (int i = 1; i <= NB; i++) s_start[tid][i] += s_start[tid][i-1];
    }
    __syncthreads();
    if (tid < 3*NB) s_off[tid/NB][tid%NB] = s_start[tid/NB][tid%NB];
    __syncthreads();
    if (tid < 3*NT) {
        int pos = atomicAdd(&s_off[lv][bid], 1);
        s_box[lv][pos]  = make_float4(cx - w*0.5f, cy - h*0.5f, cx + w*0.5f, cy + h*0.5f);
        s_meta[lv][pos] = make_float2(w*h, __int_as_float(ti | (tj<<8) | (match<<16)));
    }
    __syncthreads();

    // ---- gather tasks: warp-global id < 576 ----
    int wg = blk * NWARP + warp;
    if (wg < NGATHER) {
        int lvl = wg / (NT*NA);
        int r   = wg % (NT*NA);
        int a   = r / NT, t = r % NT;
        int gm  = s_gm[lvl][t];
        if ((gm >> (16 + a)) & 1) {
            const float* pred = (lvl==0) ? p0 : (lvl==1) ? p1 : p2;
            int HW = (lvl==0) ? HW0 : (lvl==1) ? HW1 : HW2;
            int Wd = (lvl==0) ? H0  : (lvl==1) ? H1  : H2;
            int tbid = (gm >> 19) & 7, tti = gm & 255, ttj = (gm >> 8) & 255;
            const float* pb = pred + ((tbid*NA + a)*85)*HW + ttj*Wd + tti;

            int cat = cats[t] - 1;
            float cs = 0.0f;
            for (int k = lane; k < NCLS; k += 32) {
                float xv = pb[(5 + k)*HW];
                cs += softplusf(xv) - ((k == cat) ? xv : 0.0f);
            }
            #pragma unroll
            for (int o = 16; o > 0; o >>= 1)
                cs += __shfl_down_sync(0xffffffffu, cs, o);

            if (lane == 0) {
                float4 tb = s_gbox[lvl][t];
                float px = pb[0], py = pb[HW], pw = pb[2*HW], ph = pb[3*HW], po = pb[4*HW];
                float obj_pos = softplusf(po) - po;

                float xys = c_xysc[lvl];
                float off = 0.5f * (xys - 1.0f);
                float bx = __fdividef(xys, 1.0f + __expf(-px)) - off;
                float by = __fdividef(xys, 1.0f + __expf(-py)) - off;
                float bw = __expf(pw) * c_anch[lvl][a][0];
                float bh = __expf(ph) * c_anch[lvl][a][1];

                float tx = tb.x - (float)tti, ty = tb.y - (float)ttj;
                float tw = tb.z, th = tb.w;

                float b1x1 = bx - bw*0.5f, b1x2 = bx + bw*0.5f;
                float b1y1 = by - bh*0.5f, b1y2 = by + bh*0.5f;
                float b2x1 = tx - tw*0.5f, b2x2 = tx + tw*0.5f;
                float b2y1 = ty - th*0.5f, b2y2 = ty + th*0.5f;

                float ix = fminf(b1x2, b2x2) - fmaxf(b1x1, b2x1);
                float iy = fminf(b1y2, b2y2) - fmaxf(b1y1, b2y1);
                float inter = fmaxf(ix, 0.0f) * fmaxf(iy, 0.0f);
                float uni = bw*bh + tw*th + 1e-16f - inter;
                float iou = inter / uni;

                float cw = fmaxf(b1x2, b2x2) - fminf(b1x1, b2x1);
                float ch = fmaxf(b1y2, b2y2) - fminf(b1y1, b2y1);
                float c2 = cw*cw + ch*ch + 1e-16f;
                float rho2 = (bx - tx)*(bx - tx) + (by - ty)*(by - ty);
                float dv = atanf(tw / th) - atanf(bw / bh);
                float v = FOUR_OVER_PI2 * dv * dv;
                float alpha = v / (1.0f - iou + v + 1e-16f);
                float ciou = iou - (rho2 / c2 + v * alpha);

                atomicAdd(&s_acc[0], (1.0f - ciou) * COORD_SCALE);
                atomicAdd(&s_acc[1], obj_pos);
                atomicAdd(&s_acc[2], cs);
            }
        }
    }

    // ---- cell domain: grid-stride over all levels ----
    float partial = 0.0f;
    for (int c = blk * TPB + tid; c < NCALL; c += NBLK * TPB) {
        if (c < NC0)
            partial += cell_obj<0>(p0, c,        s_box[0], s_meta[0], s_start[0]);
        else if (c < NC0 + NC1)
            partial += cell_obj<1>(p1, c - NC0,  s_box[1], s_meta[1], s_start[1]);
        else
            partial += cell_obj<2>(p2, c - NC0 - NC1, s_box[2], s_meta[2], s_start[2]);
    }

    // ---- block reduce + global accumulate ----
    #pragma unroll
    for (int o = 16; o > 0; o >>= 1)
        partial += __shfl_down_sync(0xffffffffu, partial, o);
    if (lane == 0) s_warp[warp] = partial;
    __syncthreads();
    if (tid == 0) {
        float s = 0.0f;
        #pragma unroll
        for (int i = 0; i < NWARP; i++) s += s_warp[i];
        atomicAdd(&g_acc[1], s + s_acc[1]);
        atomicAdd(&g_acc[0], s_acc[0]);
        atomicAdd(&g_acc[2], s_acc[2]);
    }

    // ---- last-block finalize: write out, reset for next graph replay ----
    if (tid == 0) {
        __threadfence();
        int tk = atomicAdd(&g_ticket, 1);
        s_last = (tk == NBLK - 1);
    }
    __syncthreads();
    if (s_last && tid == 0) {
        __threadfence();
        volatile float* ga = g_acc;
        out[0] = ga[0];  out[1] = ga[1];  out[2] = ga[2];
        ga[0] = 0.0f;  ga[1] = 0.0f;  ga[2] = 0.0f;
        g_ticket = 0;
    }
}

extern "C" void kernel_launch(void* const* d_in, const int* in_sizes, int n_in,
                              void* d_out, int out_size) {
    const float* p0      = (const float*)d_in[0];
    const float* p1      = (const float*)d_in[1];
    const float* p2      = (const float*)d_in[2];
    const float* targets = (const float*)d_in[3];
    const int*   cats    = (const int*)d_in[4];
    float* out = (float*)d_out;

    yolo_kernel<<<NBLK, TPB>>>(p0, p1, p2, targets, cats, out);
}

// round 9
// speedup vs baseline: 1.0813x; 1.0813x over previous
#include <cuda_runtime.h>
#include <math.h>

#define NT 64      // targets
#define NA 3       // anchors per level
#define NCLS 80
#define NB 8       // batch
#define TPB 256
#define NWARP (TPB/32)

#define H0 76
#define H1 38
#define H2 19
#define HW0 (H0*H0)
#define HW1 (H1*H1)
#define HW2 (H2*H2)
#define NC0 (NB*NA*HW0)   // 138624
#define NC1 (NB*NA*HW1)   // 34656
#define NC2 (NB*NA*HW2)   // 8664

#define CPB (2*TPB)              // 512 cells per block (2 per thread)
#define NBK0 ((NC0+CPB-1)/CPB)   // 271
#define NBK1 ((NC1+CPB-1)/CPB)   // 68
#define NBK2 ((NC2+CPB-1)/CPB)   // 17
#define NBKC (NBK0+NBK1+NBK2)    // 356
#define NGATHER (3*NT*NA)        // 576 warp tasks
#define NBKG (NGATHER/NWARP)     // 72
#define GRID (NBKC+NBKG)         // 428

#define IOU_T 0.213f
#define IGN_T 0.7f
#define ONE_PLUS_IGN 1.7f
#define COORD_SCALE 0.07f
#define FOUR_OVER_PI2 0.4052847345693511f

__constant__ float c_anch[3][3][2] = {
    {{1.5f, 2.0f}, {2.375f, 4.5f}, {5.0f, 3.5f}},
    {{2.25f, 4.6875f}, {4.75f, 3.4375f}, {4.5f, 9.125f}},
    {{4.4375f, 3.4375f}, {6.0f, 7.59375f}, {14.34375f, 12.53125f}}
};
__constant__ float c_invred[3] = {0.125f, 0.0625f, 0.03125f};
__constant__ float c_xysc[3]   = {1.2f, 1.1f, 1.05f};

__device__ float g_acc[3];
__device__ int   g_ticket;

__device__ __forceinline__ float softplusf(float x) {
    return fmaxf(x, 0.0f) + __logf(1.0f + __expf(-fabsf(x)));
}

// ---------------------------------------------------------------------------
// Evaluate one already-loaded cell: returns softplus(obj) if negative else 0.
// ---------------------------------------------------------------------------
template<int LVL>
__device__ __forceinline__ float eval_cell(const float* f, int x, int y, int a, int b,
    const float4* __restrict__ s_box, const float2* __restrict__ s_meta,
    const int* __restrict__ s_start)
{
    constexpr float xys = (LVL==0) ? 1.2f : (LVL==1) ? 1.1f : 1.05f;
    constexpr float off = 0.5f * (xys - 1.0f);

    float bx = __fdividef(xys, 1.0f + __expf(-f[0])) - off + (float)x;
    float by = __fdividef(xys, 1.0f + __expf(-f[1])) - off + (float)y;
    float bw = __expf(f[2]) * c_anch[LVL][a][0];
    float bh = __expf(f[3]) * c_anch[LVL][a][1];
    float bx1 = bx - bw*0.5f, bx2 = bx + bw*0.5f;
    float by1 = by - bh*0.5f, by2 = by + bh*0.5f;
    float rhs_c = IGN_T * (bw*bh + 1e-16f);

    int key = x | (y << 8);
    bool dead = false;
    int lo = s_start[b], hi = s_start[b+1];    // warp-uniform (b uniform per warp)
    for (int t = lo; t < hi; t++) {
        float4 tb = s_box[t];                  // corners x1,y1,x2,y2
        float2 tm = s_meta[t];                 // (area, packed meta)
        float ix = fminf(bx2, tb.z) - fmaxf(bx1, tb.x);
        float iy = fminf(by2, tb.w) - fmaxf(by1, tb.y);
        float inter = fmaxf(ix, 0.0f) * fmaxf(iy, 0.0f);
        // iou > IG  <=>  inter*(1+IG) > IG*(barea + tarea + eps)
        bool c1 = inter * ONE_PLUS_IGN > fmaf(IGN_T, tm.x, rhs_c);
        int mm = __float_as_int(tm.y);         // ti | tj<<8 | match<<16
        bool c2 = ((mm & 0xffff) == key) && (((mm >> (16 + a)) & 1) != 0);
        dead = dead | c1 | c2;
    }
    return dead ? 0.0f : softplusf(f[4]);
}

// ---------------------------------------------------------------------------
// Two cells per thread: decode + batch all 10 global loads before any compute.
// ---------------------------------------------------------------------------
template<int LVL>
__device__ __forceinline__ float cell_pair(const float* __restrict__ pred,
    int base, int tid,
    const float4* __restrict__ s_box, const float2* __restrict__ s_meta,
    const int* __restrict__ s_start)
{
    constexpr int Hd  = (LVL==0) ? H0 : (LVL==1) ? H1 : H2;
    constexpr int HWc = Hd * Hd;
    constexpr int NCl = NB * NA * HWc;

    int c0 = base + tid;
    int c1 = base + tid + TPB;
    bool v0 = c0 < NCl, v1 = c1 < NCl;

    int x0=0,y0=0,a0=0,b0=0, x1=0,y1=0,a1=0,b1=0;
    const float* pb0 = pred;
    const float* pb1 = pred;
    if (v0) {
        x0 = c0 % Hd; int r = c0 / Hd;
        y0 = r % Hd;  r /= Hd;
        a0 = r % NA;  b0 = r / NA;
        pb0 = pred + ((b0*NA + a0)*85)*HWc + y0*Hd + x0;
    }
    if (v1) {
        x1 = c1 % Hd; int r = c1 / Hd;
        y1 = r % Hd;  r /= Hd;
        a1 = r % NA;  b1 = r / NA;
        pb1 = pred + ((b1*NA + a1)*85)*HWc + y1*Hd + x1;
    }

    float f0[5], f1[5];
    #pragma unroll
    for (int k = 0; k < 5; k++) f0[k] = v0 ? pb0[k*HWc] : 0.0f;
    #pragma unroll
    for (int k = 0; k < 5; k++) f1[k] = v1 ? pb1[k*HWc] : 0.0f;

    float s = 0.0f;
    if (v0) s += eval_cell<LVL>(f0, x0, y0, a0, b0, s_box, s_meta, s_start);
    if (v1) s += eval_cell<LVL>(f1, x1, y1, a1, b1, s_box, s_meta, s_start);
    return s;
}

// ---------------------------------------------------------------------------
// Single launch. Block roles (static level assignment, per-level prelude):
//   [0, NBKC): cell blocks, 512 cells each (2/thread)
//   [NBKC, GRID): gather blocks, 8 warps = 8 (anchor,target) tasks
// ---------------------------------------------------------------------------
__global__ void __launch_bounds__(TPB)
yolo_kernel(const float* __restrict__ p0, const float* __restrict__ p1,
            const float* __restrict__ p2, const float* __restrict__ targets,
            const int* __restrict__ cats, float* __restrict__ out)
{
    __shared__ float4 s_box[NT];     // sorted corners
    __shared__ float2 s_meta[NT];    // sorted (area, meta)
    __shared__ float4 s_gbox[NT];    // unsorted cx,cy,w,h (gather)
    __shared__ int    s_gm[NT];      // unsorted packed meta (gather)
    __shared__ int    s_start[NB+1];
    __shared__ int    s_off[NB];
    __shared__ float  s_warp[NWARP];
    __shared__ float  s_acc[3];
    __shared__ bool   s_last;

    int tid = threadIdx.x;
    int blk = blockIdx.x;
    int warp = tid >> 5, lane = tid & 31;

    bool is_cell = blk < NBKC;
    int lvl, base = 0, gidx = 0;
    if (blk < NBK0)           { lvl = 0; base = blk*CPB; }
    else if (blk < NBK0+NBK1) { lvl = 1; base = (blk-NBK0)*CPB; }
    else if (blk < NBKC)      { lvl = 2; base = (blk-NBK0-NBK1)*CPB; }
    else                      { gidx = blk - NBKC; lvl = gidx / (NBKG/3); }

    if (tid < NB+1) s_start[tid] = 0;
    if (tid < 3)    s_acc[tid] = 0.0f;
    __syncthreads();

    // ---- per-target preprocessing for this block's level (threads 0..63) ----
    float cx = 0.f, cy = 0.f, w = 0.f, h = 0.f;
    int bid = 0, ti = 0, tj = 0, match = 0;
    if (tid < NT) {
        float ir = c_invred[lvl];
        float x1 = targets[tid*5+0]*ir, y1 = targets[tid*5+1]*ir;
        float x2 = targets[tid*5+2]*ir, y2 = targets[tid*5+3]*ir;
        bid = (int)targets[tid*5+4];
        w = x2 - x1;  h = y2 - y1;
        cx = (x1 + x2)*0.5f;  cy = (y1 + y2)*0.5f;
        ti = (int)cx;  tj = (int)cy;
        float ta = w*h;
        float ious[NA]; float best = -1.0f; int bi = 0;
        #pragma unroll
        for (int a = 0; a < NA; a++) {
            float aw = c_anch[lvl][a][0], ah = c_anch[lvl][a][1];
            float inter = fminf(aw, w) * fminf(ah, h);
            float iou = inter / (aw*ah + ta - inter);
            ious[a] = iou;
            if (iou > best) { best = iou; bi = a; }   // first-max == argmax
        }
        #pragma unroll
        for (int a = 0; a < NA; a++)
            if (ious[a] > IOU_T || a == bi) match |= 1 << a;
        atomicAdd(&s_start[bid+1], 1);
    }
    __syncthreads();

    if (is_cell) {
        // counting sort by batch-id
        if (tid == 0) {
            #pragma unroll
            for (int i = 1; i <= NB; i++) s_start[i] += s_start[i-1];
        }
        __syncthreads();
        if (tid < NB) s_off[tid] = s_start[tid];
        __syncthreads();
        if (tid < NT) {
            int pos = atomicAdd(&s_off[bid], 1);
            s_box[pos]  = make_float4(cx - w*0.5f, cy - h*0.5f, cx + w*0.5f, cy + h*0.5f);
            s_meta[pos] = make_float2(w*h, __int_as_float(ti | (tj<<8) | (match<<16)));
        }
        __syncthreads();

        float partial;
        if (lvl == 0)      partial = cell_pair<0>(p0, base, tid, s_box, s_meta, s_start);
        else if (lvl == 1) partial = cell_pair<1>(p1, base, tid, s_box, s_meta, s_start);
        else               partial = cell_pair<2>(p2, base, tid, s_box, s_meta, s_start);

        #pragma unroll
        for (int o = 16; o > 0; o >>= 1)
            partial += __shfl_down_sync(0xffffffffu, partial, o);
        if (lane == 0) s_warp[warp] = partial;
        __syncthreads();
        if (tid == 0) {
            float s = 0.0f;
            #pragma unroll
            for (int i = 0; i < NWARP; i++) s += s_warp[i];
            atomicAdd(&g_acc[1], s);
        }
    } else {
        // ---- gather path ----
        if (tid < NT) {
            s_gbox[tid] = make_float4(cx, cy, w, h);
            s_gm[tid]   = ti | (tj << 8) | (match << 16) | (bid << 19);
        }
        __syncthreads();

        int r = (gidx % (NBKG/3)) * NWARP + warp;   // 0..191
        int a = r / NT, t = r % NT;
        int gm = s_gm[t];
        if ((gm >> (16 + a)) & 1) {
            const float* pred = (lvl==0) ? p0 : (lvl==1) ? p1 : p2;
            int HW = (lvl==0) ? HW0 : (lvl==1) ? HW1 : HW2;
            int Wd = (lvl==0) ? H0  : (lvl==1) ? H1  : H2;
            int tbid = (gm >> 19) & 7, tti = gm & 255, ttj = (gm >> 8) & 255;
            const float* pb = pred + ((tbid*NA + a)*85)*HW + ttj*Wd + tti;

            int cat = cats[t] - 1;
            float cs = 0.0f;
            for (int k = lane; k < NCLS; k += 32) {
                float xv = pb[(5 + k)*HW];
                cs += softplusf(xv) - ((k == cat) ? xv : 0.0f);
            }
            #pragma unroll
            for (int o = 16; o > 0; o >>= 1)
                cs += __shfl_down_sync(0xffffffffu, cs, o);

            if (lane == 0) {
                float4 tb = s_gbox[t];
                float px = pb[0], py = pb[HW], pw = pb[2*HW], ph = pb[3*HW], po = pb[4*HW];
                float obj_pos = softplusf(po) - po;

                float xys = c_xysc[lvl];
                float off = 0.5f * (xys - 1.0f);
                float bx = __fdividef(xys, 1.0f + __expf(-px)) - off;
                float by = __fdividef(xys, 1.0f + __expf(-py)) - off;
                float bw = __expf(pw) * c_anch[lvl][a][0];
                float bh = __expf(ph) * c_anch[lvl][a][1];

                float tx = tb.x - (float)tti, ty = tb.y - (float)ttj;
                float tw = tb.z, th = tb.w;

                float b1x1 = bx - bw*0.5f, b1x2 = bx + bw*0.5f;
                float b1y1 = by - bh*0.5f, b1y2 = by + bh*0.5f;
                float b2x1 = tx - tw*0.5f, b2x2 = tx + tw*0.5f;
                float b2y1 = ty - th*0.5f, b2y2 = ty + th*0.5f;

                float ix = fminf(b1x2, b2x2) - fmaxf(b1x1, b2x1);
                float iy = fminf(b1y2, b2y2) - fmaxf(b1y1, b2y1);
                float inter = fmaxf(ix, 0.0f) * fmaxf(iy, 0.0f);
                float uni = bw*bh + tw*th + 1e-16f - inter;
                float iou = inter / uni;

                float cw = fmaxf(b1x2, b2x2) - fminf(b1x1, b2x1);
                float ch = fmaxf(b1y2, b2y2) - fminf(b1y1, b2y1);
                float c2 = cw*cw + ch*ch + 1e-16f;
                float rho2 = (bx - tx)*(bx - tx) + (by - ty)*(by - ty);
                float dv = atanf(tw / th) - atanf(bw / bh);
                float v = FOUR_OVER_PI2 * dv * dv;
                float alpha = v / (1.0f - iou + v + 1e-16f);
                float ciou = iou - (rho2 / c2 + v * alpha);

                atomicAdd(&s_acc[0], (1.0f - ciou) * COORD_SCALE);
                atomicAdd(&s_acc[1], obj_pos);
                atomicAdd(&s_acc[2], cs);
            }
        }
        __syncthreads();
        if (tid == 0) {
            atomicAdd(&g_acc[0], s_acc[0]);
            atomicAdd(&g_acc[1], s_acc[1]);
            atomicAdd(&g_acc[2], s_acc[2]);
        }
    }

    // ---- last-block finalize ----
    if (tid == 0) {
        __threadfence();
        int tk = atomicAdd(&g_ticket, 1);
        s_last = (tk == GRID - 1);
    }
    __syncthreads();
    if (s_last && tid == 0) {
        __threadfence();
        volatile float* ga = g_acc;
        out[0] = ga[0];  out[1] = ga[1];  out[2] = ga[2];
        ga[0] = 0.0f;  ga[1] = 0.0f;  ga[2] = 0.0f;
        g_ticket = 0;
    }
}

extern "C" void kernel_launch(void* const* d_in, const int* in_sizes, int n_in,
                              void* d_out, int out_size) {
    const float* p0      = (const float*)d_in[0];
    const float* p1      = (const float*)d_in[1];
    const float* p2      = (const float*)d_in[2];
    const float* targets = (const float*)d_in[3];
    const int*   cats    = (const int*)d_in[4];
    float* out = (float*)d_out;

    yolo_kernel<<<GRID, TPB>>>(p0, p1, p2, targets, cats, out);
}

// round 10
// speedup vs baseline: 1.1599x; 1.0727x over previous
#include <cuda_runtime.h>
#include <math.h>

#define NT 64
#define NA 3
#define NCLS 80
#define NB 8
#define TPB 256
#define NWARP (TPB/32)

#define H0 76
#define H1 38
#define H2 19
#define HW0 (H0*H0)   // 5776
#define HW1 (H1*H1)   // 1444
#define HW2 (H2*H2)   // 361

#define CH0 ((HW0+TPB-1)/TPB)    // 23 chunks per plane
#define CH1 ((HW1+TPB-1)/TPB)    // 6
#define CH2 ((HW2+TPB-1)/TPB)    // 2
#define NPL (NB*NA)              // 24 planes per level
#define NBK0 (NPL*CH0)           // 552
#define NBK1 (NPL*CH1)           // 144
#define NBK2 (NPL*CH2)           // 48
#define NBKC (NBK0+NBK1+NBK2)    // 744
#define NBKG_L (NT*NA/NWARP)     // 24 gather blocks per level
#define NBKG (3*NBKG_L)          // 72
#define GRID (NBKC+NBKG)         // 816

#define IOU_T 0.213f
#define IGN_T 0.7f
#define ONE_PLUS_IGN 1.7f
#define COORD_SCALE 0.07f
#define FOUR_OVER_PI2 0.4052847345693511f
// candidacy pads (conservative: |dc| < 0.8205*wT, center in (x-0.1, x+1.1))
#define CPAD_W 0.8206f
#define CPAD_LO 1.11f
#define CPAD_HI 0.11f

__constant__ float c_anch[3][3][2] = {
    {{1.5f, 2.0f}, {2.375f, 4.5f}, {5.0f, 3.5f}},
    {{2.25f, 4.6875f}, {4.75f, 3.4375f}, {4.5f, 9.125f}},
    {{4.4375f, 3.4375f}, {6.0f, 7.59375f}, {14.34375f, 12.53125f}}
};
__constant__ float c_invred[3] = {0.125f, 0.0625f, 0.03125f};
__constant__ float c_xysc[3]   = {1.2f, 1.1f, 1.05f};

__device__ float g_acc[3];
__device__ int   g_ticket;

__device__ __forceinline__ float softplusf(float x) {
    return fmaxf(x, 0.0f) + __logf(1.0f + __expf(-fabsf(x)));
}

// ---------------------------------------------------------------------------
// Cell worker: one cell/thread, block confined to one (b,a) plane.
// Returns softplus(obj) if cell is NOT ignored (positives corrected by gather).
// ---------------------------------------------------------------------------
template<int LVL>
__device__ __forceinline__ float cell_work(const float* __restrict__ pred,
    int relblk, int tid,
    const float4* __restrict__ s_cand, const float4* __restrict__ s_box,
    const float* __restrict__ s_area, const int* __restrict__ s_start)
{
    constexpr int   Hd  = (LVL==0) ? H0 : (LVL==1) ? H1 : H2;
    constexpr int   HWc = Hd * Hd;
    constexpr int   CHK = (HWc + TPB - 1) / TPB;
    constexpr float xys = (LVL==0) ? 1.2f : (LVL==1) ? 1.1f : 1.05f;
    constexpr float off = 0.5f * (xys - 1.0f);

    int pl    = relblk / CHK;         // b*NA + a  (warp-uniform)
    int chunk = relblk % CHK;
    int qr    = chunk * TPB + tid;
    bool valid = qr < HWc;
    int q = valid ? qr : 0;
    int x = q % Hd, y = q / Hd;
    int a = pl % NA, b = pl / NA;

    const float* pb = pred + pl * 85 * HWc + q;
    float f0 = pb[0], f1 = pb[HWc], f2 = pb[2*HWc], f3 = pb[3*HWc], po = pb[4*HWc];

    float bx = __fdividef(xys, 1.0f + __expf(-f0)) - off + (float)x;
    float by = __fdividef(xys, 1.0f + __expf(-f1)) - off + (float)y;
    float bw = __expf(f2) * c_anch[LVL][a][0];
    float bh = __expf(f3) * c_anch[LVL][a][1];
    float bx1 = bx - bw*0.5f, bx2 = bx + bw*0.5f;
    float by1 = by - bh*0.5f, by2 = by + bh*0.5f;
    float rhs_c = IGN_T * (bw*bh + 1e-16f);

    float fx = (float)x, fy = (float)y;
    bool dead = false;
    int lo = s_start[b], hi = s_start[b+1];    // warp-uniform
    for (int t = lo; t < hi; t++) {
        float4 cd = s_cand[t];
        bool cand = (fx > cd.x) && (fx < cd.z) && (fy > cd.y) && (fy < cd.w);
        if (__any_sync(0xffffffffu, cand)) {
            float4 tb = s_box[t];
            float aT = s_area[t];
            float ix = fminf(bx2, tb.z) - fmaxf(bx1, tb.x);
            float iy = fminf(by2, tb.w) - fmaxf(by1, tb.y);
            float inter = fmaxf(ix, 0.0f) * fmaxf(iy, 0.0f);
            dead = dead | (inter * ONE_PLUS_IGN > fmaf(IGN_T, aT, rhs_c));
        }
    }
    return (valid && !dead) ? softplusf(po) : 0.0f;
}

// ---------------------------------------------------------------------------
// Single launch, 816 blocks:
//   [0,744): cell blocks (plane-aligned, 1 cell/thread)
//   [744,816): gather blocks, 8 warps = (anchor,target) tasks + obj_neg correction
// ---------------------------------------------------------------------------
__global__ void __launch_bounds__(TPB)
yolo_kernel(const float* __restrict__ p0, const float* __restrict__ p1,
            const float* __restrict__ p2, const float* __restrict__ targets,
            const int* __restrict__ cats, float* __restrict__ out)
{
    __shared__ float4 s_cand[NT];    // bucketed candidate rects (cell path)
    __shared__ float4 s_box[NT];     // corners: bucketed (cell) / by-t (gather)
    __shared__ float  s_area[NT];
    __shared__ float4 s_gbox[NT];    // cx,cy,w,h by-t (gather)
    __shared__ int    s_gm[NT];      // packed meta by-t (gather)
    __shared__ int    s_start[NB+1];
    __shared__ int    s_off[NB];
    __shared__ float  s_warp[NWARP];
    __shared__ float  s_acc[3];
    __shared__ bool   s_last;

    int tid = threadIdx.x;
    int blk = blockIdx.x;
    int warp = tid >> 5, lane = tid & 31;

    bool is_cell = blk < NBKC;
    int lvl, rel = 0, gidx = 0;
    if (blk < NBK0)           { lvl = 0; rel = blk; }
    else if (blk < NBK0+NBK1) { lvl = 1; rel = blk - NBK0; }
    else if (blk < NBKC)      { lvl = 2; rel = blk - NBK0 - NBK1; }
    else                      { gidx = blk - NBKC; lvl = gidx / NBKG_L; }

    if (tid < NB+1) s_start[tid] = 0;
    if (tid < 3)    s_acc[tid] = 0.0f;
    __syncthreads();

    // ---- per-target preprocessing (threads 0..63), this block's level ----
    float cx = 0.f, cy = 0.f, w = 0.f, h = 0.f;
    int bid = 0;
    if (tid < NT) {
        float ir = c_invred[lvl];
        float x1 = targets[tid*5+0]*ir, y1 = targets[tid*5+1]*ir;
        float x2 = targets[tid*5+2]*ir, y2 = targets[tid*5+3]*ir;
        bid = (int)targets[tid*5+4];
        w = x2 - x1;  h = y2 - y1;
        cx = (x1 + x2)*0.5f;  cy = (y1 + y2)*0.5f;
        if (is_cell) atomicAdd(&s_start[bid+1], 1);
    }
    __syncthreads();

    if (is_cell) {
        if (tid == 0) {
            #pragma unroll
            for (int i = 1; i <= NB; i++) s_start[i] += s_start[i-1];
        }
        __syncthreads();
        if (tid < NB) s_off[tid] = s_start[tid];
        __syncthreads();
        if (tid < NT) {
            int pos = atomicAdd(&s_off[bid], 1);
            s_box[pos]  = make_float4(cx - w*0.5f, cy - h*0.5f, cx + w*0.5f, cy + h*0.5f);
            s_area[pos] = w*h;
            s_cand[pos] = make_float4(cx - CPAD_W*w - CPAD_LO, cy - CPAD_W*h - CPAD_LO,
                                      cx + CPAD_W*w + CPAD_HI, cy + CPAD_W*h + CPAD_HI);
        }
        __syncthreads();

        float partial;
        if (lvl == 0)      partial = cell_work<0>(p0, rel, tid, s_cand, s_box, s_area, s_start);
        else if (lvl == 1) partial = cell_work<1>(p1, rel, tid, s_cand, s_box, s_area, s_start);
        else               partial = cell_work<2>(p2, rel, tid, s_cand, s_box, s_area, s_start);

        #pragma unroll
        for (int o = 16; o > 0; o >>= 1)
            partial += __shfl_down_sync(0xffffffffu, partial, o);
        if (lane == 0) s_warp[warp] = partial;
        __syncthreads();
        if (tid == 0) {
            float s = 0.0f;
            #pragma unroll
            for (int i = 0; i < NWARP; i++) s += s_warp[i];
            atomicAdd(&g_acc[1], s);
        }
    } else {
        // gather prelude: per-target data indexed by t (unsorted) + anchor match
        if (tid < NT) {
            int ti = (int)cx, tj = (int)cy;
            float ta = w*h;
            float ious[NA]; float best = -1.0f; int bi = 0;
            #pragma unroll
            for (int aa = 0; aa < NA; aa++) {
                float aw = c_anch[lvl][aa][0], ah = c_anch[lvl][aa][1];
                float inter = fminf(aw, w) * fminf(ah, h);
                float iou = inter / (aw*ah + ta - inter);
                ious[aa] = iou;
                if (iou > best) { best = iou; bi = aa; }   // first-max == argmax
            }
            int match = 0;
            #pragma unroll
            for (int aa = 0; aa < NA; aa++)
                if (ious[aa] > IOU_T || aa == bi) match |= 1 << aa;
            s_gbox[tid] = make_float4(cx, cy, w, h);
            s_gm[tid]   = ti | (tj << 8) | (match << 16) | (bid << 19);
            s_box[tid]  = make_float4(cx - w*0.5f, cy - h*0.5f, cx + w*0.5f, cy + h*0.5f);
            s_area[tid] = ta;
        }
        __syncthreads();

        int r = (gidx % NBKG_L) * NWARP + warp;   // 0..191
        int a = r / NT, t = r % NT;
        int gm = s_gm[t];
        if ((gm >> (16 + a)) & 1) {               // warp-uniform
            const float* pred = (lvl==0) ? p0 : (lvl==1) ? p1 : p2;
            int HW = (lvl==0) ? HW0 : (lvl==1) ? HW1 : HW2;
            int Wd = (lvl==0) ? H0  : (lvl==1) ? H1  : H2;
            int tbid = (gm >> 19) & 7, tti = gm & 255, ttj = (gm >> 8) & 255;
            const float* pb = pred + ((tbid*NA + a)*85)*HW + ttj*Wd + tti;

            // class BCE across warp
            int cat = cats[t] - 1;
            float cs = 0.0f;
            for (int k = lane; k < NCLS; k += 32) {
                float xv = pb[(5 + k)*HW];
                cs += softplusf(xv) - ((k == cat) ? xv : 0.0f);
            }
            #pragma unroll
            for (int o = 16; o > 0; o >>= 1)
                cs += __shfl_down_sync(0xffffffffu, cs, o);

            // all lanes: pred box (uniform loads) for ignore-test + dedup
            float px = pb[0], py = pb[HW], pw = pb[2*HW], ph = pb[3*HW], po = pb[4*HW];
            float xys = c_xysc[lvl];
            float offv = 0.5f * (xys - 1.0f);
            float bxl = __fdividef(xys, 1.0f + __expf(-px)) - offv;   // local
            float byl = __fdividef(xys, 1.0f + __expf(-py)) - offv;
            float bw = __expf(pw) * c_anch[lvl][a][0];
            float bh = __expf(ph) * c_anch[lvl][a][1];
            // global-coord corners: identical arithmetic to cell path
            float bxf = bxl + (float)tti, byf = byl + (float)ttj;
            float gx1 = bxf - bw*0.5f, gx2 = bxf + bw*0.5f;
            float gy1 = byf - bh*0.5f, gy2 = byf + bh*0.5f;
            float rhs_c = IGN_T * (bw*bh + 1e-16f);

            unsigned ign_mask = 0, dup_mask = 0;
            #pragma unroll
            for (int half = 0; half < 2; half++) {
                int t2 = lane + 32*half;
                int gm2 = s_gm[t2];
                bool ig = false;
                if (((gm2 ^ gm) & 0x00380000) == 0) {   // same batch image
                    float4 tb = s_box[t2];
                    float ix = fminf(gx2, tb.z) - fmaxf(gx1, tb.x);
                    float iy = fminf(gy2, tb.w) - fmaxf(gy1, tb.y);
                    float inter = fmaxf(ix, 0.0f) * fmaxf(iy, 0.0f);
                    ig = inter * ONE_PLUS_IGN > fmaf(IGN_T, s_area[t2], rhs_c);
                }
                bool dp = (t2 < t) && (((gm2 ^ gm) & 0x0038FFFF) == 0)
                          && (((gm2 >> (16 + a)) & 1) != 0);
                ign_mask |= __ballot_sync(0xffffffffu, ig);
                dup_mask |= __ballot_sync(0xffffffffu, dp);
            }

            if (lane == 0) {
                float obj_pos = softplusf(po) - po;
                // correction: main pass added softplus(po) iff !ignored; positives excluded once
                float corr = (ign_mask == 0 && dup_mask == 0) ? softplusf(po) : 0.0f;

                float4 tb = s_gbox[t];
                float tx = tb.x - (float)tti, ty = tb.y - (float)ttj;
                float tw = tb.z, th = tb.w;

                float b1x1 = bxl - bw*0.5f, b1x2 = bxl + bw*0.5f;
                float b1y1 = byl - bh*0.5f, b1y2 = byl + bh*0.5f;
                float b2x1 = tx - tw*0.5f, b2x2 = tx + tw*0.5f;
                float b2y1 = ty - th*0.5f, b2y2 = ty + th*0.5f;

                float ix = fminf(b1x2, b2x2) - fmaxf(b1x1, b2x1);
                float iy = fminf(b1y2, b2y2) - fmaxf(b1y1, b2y1);
                float inter = fmaxf(ix, 0.0f) * fmaxf(iy, 0.0f);
                float uni = bw*bh + tw*th + 1e-16f - inter;
                float iou = inter / uni;

                float cw = fmaxf(b1x2, b2x2) - fminf(b1x1, b2x1);
                float ch = fmaxf(b1y2, b2y2) - fminf(b1y1, b2y1);
                float c2 = cw*cw + ch*ch + 1e-16f;
                float rho2 = (bxl - tx)*(bxl - tx) + (byl - ty)*(byl - ty);
                float dv = atanf(tw / th) - atanf(bw / bh);
                float v = FOUR_OVER_PI2 * dv * dv;
                float alpha = v / (1.0f - iou + v + 1e-16f);
                float ciou = iou - (rho2 / c2 + v * alpha);

                atomicAdd(&s_acc[0], (1.0f - ciou) * COORD_SCALE);
                atomicAdd(&s_acc[1], obj_pos - corr);
                atomicAdd(&s_acc[2], cs);
            }
        }
        __syncthreads();
        if (tid == 0) {
            atomicAdd(&g_acc[0], s_acc[0]);
            atomicAdd(&g_acc[1], s_acc[1]);
            atomicAdd(&g_acc[2], s_acc[2]);
        }
    }

    // ---- last-block finalize ----
    if (tid == 0) {
        __threadfence();
        int tk = atomicAdd(&g_ticket, 1);
        s_last = (tk == GRID - 1);
    }
    __syncthreads();
    if (s_last && tid == 0) {
        __threadfence();
        volatile float* ga = g_acc;
        out[0] = ga[0];  out[1] = ga[1];  out[2] = ga[2];
        ga[0] = 0.0f;  ga[1] = 0.0f;  ga[2] = 0.0f;
        g_ticket = 0;
    }
}

extern "C" void kernel_launch(void* const* d_in, const int* in_sizes, int n_in,
                              void* d_out, int out_size) {
    const float* p0      = (const float*)d_in[0];
    const float* p1      = (const float*)d_in[1];
    const float* p2      = (const float*)d_in[2];
    const float* targets = (const float*)d_in[3];
    const int*   cats    = (const int*)d_in[4];
    float* out = (float*)d_out;

    yolo_kernel<<<GRID, TPB>>>(p0, p1, p2, targets, cats, out);
}